// round 9
// baseline (speedup 1.0000x reference)
#include <cuda_runtime.h>
#include <cuda_bf16.h>
#include <math.h>
#include <stdint.h>

#define B 128
#define T 2048
#define H 200
#define G4 800
#define NSTEP 5

// ---- scratch ----
__device__ float g_qproj[B * H];
__device__ float g_gbase[B * G4];   // full gate base: ctx@Wih' + q@Whh' + bih + bhh
__device__ float g_scores[B * T];
__device__ float g_context[B * H];

__device__ __forceinline__ float tanh_fast(float x) {
    float e = __expf(2.0f * x);
    return 1.0f - __fdividef(2.0f, e + 1.0f);
}
__device__ __forceinline__ float sig_fast(float x) {
    return __fdividef(1.0f, 1.0f + __expf(-x));
}
__device__ __forceinline__ uint32_t smem_u32(const void* p) {
    uint32_t a;
    asm("{ .reg .u64 t; cvta.to.shared.u64 t, %1; cvt.u32.u64 %0, t; }" : "=r"(a) : "l"(p));
    return a;
}
__device__ __forceinline__ void cp_async16(uint32_t dst, const void* src, uint32_t src_sz) {
    asm volatile("cp.async.cg.shared.global [%0], [%1], 16, %2;"
                 :: "r"(dst), "l"(src), "r"(src_sz) : "memory");
}
__device__ __forceinline__ void mma_tf32(float* d, const uint32_t* a, const uint32_t* b) {
    asm volatile("mma.sync.aligned.m16n8k8.row.col.f32.tf32.tf32.f32 "
                 "{%0,%1,%2,%3}, {%4,%5,%6,%7}, {%8,%9}, {%0,%1,%2,%3};"
                 : "+f"(d[0]), "+f"(d[1]), "+f"(d[2]), "+f"(d[3])
                 : "r"(a[0]), "r"(a[1]), "r"(a[2]), "r"(a[3]), "r"(b[0]), "r"(b[1]));
}
#define LDSM4(r, a) \
    asm volatile("ldmatrix.sync.aligned.m8n8.x4.shared.b16 {%0,%1,%2,%3}, [%4];" \
                 : "=r"((r)[0]), "=r"((r)[1]), "=r"((r)[2]), "=r"((r)[3]) : "r"(a))
#define LDSM2(r, a) \
    asm volatile("ldmatrix.sync.aligned.m8n8.x2.shared.b16 {%0,%1}, [%2];" \
                 : "=r"((r)[0]), "=r"((r)[1]) : "r"(a))

// ============================================================
// Kernel 1: qproj = h0 @ Wa.T + ba   (batch-tiled, weight-row reuse x4)
// grid (2, 16), block (100, 2)
// ============================================================
__global__ void k_pre(const float* __restrict__ h0, const float* __restrict__ Wa,
                      const float* __restrict__ ba) {
    __shared__ float sQT[8][200];
    const int tid = threadIdx.y * 100 + threadIdx.x;
    const int g   = blockIdx.x * 100 + threadIdx.x;
    const int b0  = blockIdx.y * 8;
    const int half = threadIdx.y;

    for (int i = tid; i < 8 * 200; i += 200) sQT[i / 200][i % 200] = h0[(b0 + i / 200) * H + i % 200];
    __syncthreads();

    const float* w = Wa + g * H;
    float acc[4];
    #pragma unroll
    for (int bb = 0; bb < 4; ++bb) acc[bb] = ba[g];
    for (int k = 0; k < H; ++k) {
        const float wv = w[k];
        #pragma unroll
        for (int bb = 0; bb < 4; ++bb) acc[bb] += wv * sQT[half * 4 + bb][k];
    }
    #pragma unroll
    for (int bb = 0; bb < 4; ++bb) g_qproj[(b0 + half * 4 + bb) * H + g] = acc[bb];
}

// ============================================================
// Kernel 2: score GEMM. z=1 (full N=208), mma.sync tf32, ldmatrix
// fragments, 3-stage cp.async ring (dynamic smem, 83 KB).
// Grid (16, 128), 256 threads, 1 CTA/SM.
// ============================================================
#define SSTR 20                 // row stride in words
#define STAGE_WORDS (336 * SSTR)  // 128 A rows + 208 B rows
#define STAGE_BYTES (STAGE_WORDS * 4)
#define NKCH 13
#define SMEM_WORDS (3 * STAGE_WORDS + 208 + 208 + 128)
#define SMEM_BYTES (SMEM_WORDS * 4)

__global__ __launch_bounds__(256, 1)
void k_scores_mma(const float* __restrict__ enc, const float* __restrict__ Ua,
                  const float* __restrict__ bua, const float* __restrict__ Va) {
    extern __shared__ __align__(16) uint32_t dsm[];
    float* sQ   = (float*)(dsm + 3 * STAGE_WORDS);
    float* sV   = sQ + 208;
    float* sRow = sV + 208;

    const int tid  = threadIdx.x;
    const int wid  = tid >> 5, lane = tid & 31;
    const int b    = blockIdx.y;
    const int t0   = blockIdx.x * 128;

    const int mw = wid & 3;            // 4 m-stripes of 32 rows
    const int nw = wid >> 2;           // 2 n-stripes of 104 cols
    const int rowbase = mw * 32;
    const int nbase   = nw * 104;
    const int q = lane >> 2;
    const int c = lane & 3;

    for (int i = tid; i < 208; i += 256) {
        sQ[i] = (i < H) ? g_qproj[b * H + i] + bua[i] : 0.f;
        sV[i] = (i < H) ? Va[i] : 0.f;
    }
    if (tid < 128) sRow[tid] = 0.f;

    float acc[2][13][4];
    #pragma unroll
    for (int mt = 0; mt < 2; ++mt)
        #pragma unroll
        for (int nt = 0; nt < 13; ++nt)
            #pragma unroll
            for (int j = 0; j < 4; ++j) acc[mt][nt][j] = 0.f;

    const float* encB = enc + ((long)b * T + t0) * H;
    const uint32_t smemBase = smem_u32(dsm);

    // ldmatrix per-lane base addresses (stage 0, kk 0)
    const uint32_t aBase0 = smemBase +
        (uint32_t)(((rowbase + (lane & 15)) * SSTR + 4 * (lane >> 4)) * 4);
    const uint32_t bBase = smemBase +
        (uint32_t)(((128 + nbase + (lane & 7) + 8 * ((lane >> 4) & 1)) * SSTR
                    + 4 * ((lane >> 3) & 1)) * 4);

    auto fill = [&](int kc, int st) {
        const int k0 = kc * 16;
        const uint32_t stOff = smemBase + (uint32_t)st * STAGE_BYTES;
        for (int i = tid; i < 128 * 4; i += 256) {          // A
            const int row = i >> 2, g = i & 3;
            const int gk = k0 + g * 4;
            const bool ok = (gk + 4 <= H);
            const float* src = ok ? (encB + (long)row * H + gk) : encB;
            cp_async16(stOff + (uint32_t)((row * SSTR + g * 4) * 4), src, ok ? 16u : 0u);
        }
        for (int i = tid; i < 208 * 4; i += 256) {          // B
            const int row = i >> 2, g = i & 3;
            const int gk = k0 + g * 4;
            const bool ok = (row < H) && (gk + 4 <= H);
            const float* src = ok ? (Ua + (long)row * H + gk) : Ua;
            cp_async16(stOff + (uint32_t)(((128 + row) * SSTR + g * 4) * 4), src, ok ? 16u : 0u);
        }
        asm volatile("cp.async.commit_group;" ::: "memory");
    };

    fill(0, 0);
    fill(1, 1);

    for (int kc = 0; kc < NKCH; ++kc) {
        const int st = kc % 3;
        if (kc + 2 < NKCH) fill(kc + 2, (kc + 2) % 3);

        if (kc + 2 < NKCH)      asm volatile("cp.async.wait_group 2;" ::: "memory");
        else if (kc + 1 < NKCH) asm volatile("cp.async.wait_group 1;" ::: "memory");
        else                    asm volatile("cp.async.wait_group 0;" ::: "memory");
        __syncthreads();

        const uint32_t stB = (uint32_t)st * STAGE_BYTES;
        #pragma unroll
        for (int ks = 0; ks < 2; ++ks) {
            const uint32_t kkB = (uint32_t)(ks * 8 * 4);
            uint32_t a0[4], a1[4];
            LDSM4(a0, aBase0 + stB + kkB);
            LDSM4(a1, aBase0 + stB + kkB + 16 * SSTR * 4);
            const uint32_t bA = bBase + stB + kkB;
            #pragma unroll
            for (int ntp = 0; ntp < 6; ++ntp) {
                uint32_t b4[4];
                LDSM4(b4, bA + (uint32_t)(ntp * 2 * 8 * SSTR * 4));
                mma_tf32(acc[0][2 * ntp],     a0, b4);
                mma_tf32(acc[0][2 * ntp + 1], a0, b4 + 2);
                mma_tf32(acc[1][2 * ntp],     a1, b4);
                mma_tf32(acc[1][2 * ntp + 1], a1, b4 + 2);
            }
            {
                uint32_t b2[2];
                LDSM2(b2, bA + (uint32_t)(12 * 8 * SSTR * 4));
                mma_tf32(acc[0][12], a0, b2);
                mma_tf32(acc[1][12], a1, b2);
            }
        }
        __syncthreads();
    }

    // ---- epilogue: tanh + Va reduce ----
    float pLo[2], pHi[2];
    #pragma unroll
    for (int mt = 0; mt < 2; ++mt) { pLo[mt] = 0.f; pHi[mt] = 0.f; }
    #pragma unroll
    for (int nt = 0; nt < 13; ++nt) {
        const int col0 = nbase + nt * 8 + c * 2;
        const float v0 = sV[col0],     q0 = sQ[col0];
        const float v1 = sV[col0 + 1], q1 = sQ[col0 + 1];
        #pragma unroll
        for (int mt = 0; mt < 2; ++mt) {
            pLo[mt] += v0 * tanh_fast(q0 + acc[mt][nt][0]) + v1 * tanh_fast(q1 + acc[mt][nt][1]);
            pHi[mt] += v0 * tanh_fast(q0 + acc[mt][nt][2]) + v1 * tanh_fast(q1 + acc[mt][nt][3]);
        }
    }
    #pragma unroll
    for (int mt = 0; mt < 2; ++mt) {
        #pragma unroll
        for (int o = 1; o <= 2; o <<= 1) {
            pLo[mt] += __shfl_xor_sync(0xffffffffu, pLo[mt], o);
            pHi[mt] += __shfl_xor_sync(0xffffffffu, pHi[mt], o);
        }
        if (c == 0) {
            const int R = rowbase + mt * 16 + q;
            atomicAdd(&sRow[R], pLo[mt]);
            atomicAdd(&sRow[R + 8], pHi[mt]);
        }
    }
    __syncthreads();
    if (tid < 128) g_scores[b * T + t0 + tid] = sRow[tid];
}

// ============================================================
// Kernel 3: softmax + context. 800 threads, unroll 8 (MLP).
// ============================================================
#define CTXTH 800

__global__ void k_ctx(const float* __restrict__ enc) {
    __shared__ float sW[T];
    __shared__ float sP[4][H];
    __shared__ float red[32];
    const int b = blockIdx.x, tid = threadIdx.x;
    const int lane = tid & 31, wid = tid >> 5;

    float m = -1e30f;
    for (int t = tid; t < T; t += CTXTH) { float s = g_scores[b * T + t]; sW[t] = s; m = fmaxf(m, s); }
    #pragma unroll
    for (int o = 16; o; o >>= 1) m = fmaxf(m, __shfl_xor_sync(0xffffffffu, m, o));
    if (lane == 0) red[wid] = m;
    __syncthreads();
    if (tid < 32) {
        float w = (tid < CTXTH / 32) ? red[tid] : -1e30f;
        #pragma unroll
        for (int o = 16; o; o >>= 1) w = fmaxf(w, __shfl_xor_sync(0xffffffffu, w, o));
        if (tid == 0) red[0] = w;
    }
    __syncthreads();
    m = red[0];
    __syncthreads();

    float sum = 0.f;
    for (int t = tid; t < T; t += CTXTH) { float e = __expf(sW[t] - m); sW[t] = e; sum += e; }
    #pragma unroll
    for (int o = 16; o; o >>= 1) sum += __shfl_xor_sync(0xffffffffu, sum, o);
    if (lane == 0) red[wid] = sum;
    __syncthreads();
    if (tid < 32) {
        float w = (tid < CTXTH / 32) ? red[tid] : 0.f;
        #pragma unroll
        for (int o = 16; o; o >>= 1) w += __shfl_xor_sync(0xffffffffu, w, o);
        if (tid == 0) red[0] = w;
    }
    __syncthreads();
    const float inv = __fdividef(1.0f, red[0]);

    const int sl = tid / H;
    const int h  = tid - sl * H;
    const float* eB = enc + (long)b * T * H + h;
    float a[8];
    #pragma unroll
    for (int j = 0; j < 8; ++j) a[j] = 0.f;
    const int tbeg = sl * (T / 4), tend = tbeg + (T / 4);
    for (int t = tbeg; t < tend; t += 8) {
        #pragma unroll
        for (int j = 0; j < 8; ++j) a[j] += sW[t + j] * eB[(long)(t + j) * H];
    }
    sP[sl][h] = ((a[0] + a[1]) + (a[2] + a[3])) + ((a[4] + a[5]) + (a[6] + a[7]));
    __syncthreads();
    if (tid < H)
        g_context[b * H + tid] = (sP[0][tid] + sP[1][tid] + sP[2][tid] + sP[3][tid]) * inv;
}

// ============================================================
// Kernel 3.5: gate base GEMM (ctx@Wih[:,1:]' + q@Whh' + bih + bhh).
// grid (8, 16), block (100, 2); weight rows reused x4 batches.
// ============================================================
__global__ void k_gates(const float* __restrict__ h0, const float* __restrict__ Wih,
                        const float* __restrict__ Whh, const float* __restrict__ bih,
                        const float* __restrict__ bhh) {
    __shared__ float sC[8][200];
    __shared__ float sQT[8][200];
    const int tid = threadIdx.y * 100 + threadIdx.x;
    const int g   = blockIdx.x * 100 + threadIdx.x;
    const int b0  = blockIdx.y * 8;
    const int half = threadIdx.y;

    for (int i = tid; i < 8 * 200; i += 200) {
        const int r = i / 200, k = i % 200;
        sC[r][k]  = g_context[(b0 + r) * H + k];
        sQT[r][k] = h0[(b0 + r) * H + k];
    }
    __syncthreads();

    const float* wih = Wih + g * (H + 1) + 1;
    const float* whh = Whh + g * H;
    float acc[4];
    const float bias = bih[g] + bhh[g];
    #pragma unroll
    for (int bb = 0; bb < 4; ++bb) acc[bb] = bias;
    for (int k = 0; k < H; ++k) {
        const float wv = wih[k];
        const float wh = whh[k];
        #pragma unroll
        for (int bb = 0; bb < 4; ++bb) {
            const int r = half * 4 + bb;
            acc[bb] += wv * sC[r][k] + wh * sQT[r][k];
        }
    }
    #pragma unroll
    for (int bb = 0; bb < 4; ++bb)
        g_gbase[(b0 + half * 4 + bb) * G4 + g] = acc[bb];
}

// ============================================================
// Kernel 4: decoder. Gates precomputed; steps touch only smem/regs.
// ============================================================
__global__ void k_dec(const float* __restrict__ x, const float* __restrict__ c0in,
                      const float* __restrict__ Wih,
                      const float* __restrict__ W1, const float* __restrict__ b1,
                      const float* __restrict__ W2, const float* __restrict__ b2,
                      const float* __restrict__ W3, const float* __restrict__ b3,
                      float* __restrict__ out) {
    __shared__ float sGB[G4];
    __shared__ float sWx[G4];
    __shared__ float sR[H];
    __shared__ float sO1[100];
    __shared__ float sO2[52];
    __shared__ float sRed[64];
    __shared__ float sY;
    __shared__ float sW2[5000];
    __shared__ float sW3[52];
    __shared__ float sB1[100];
    __shared__ float sB2c[52];

    const int b = blockIdx.x, tid = threadIdx.x;
    const int lane = tid & 31;
    const unsigned m8  = 0xFFu   << (lane & 24);
    const unsigned m16 = 0xFFFFu << (lane & 16);

    for (int i = tid; i < 5000; i += G4) sW2[i] = W2[i];
    if (tid < 50)  sW3[tid] = W3[tid];
    if (tid < 100) sB1[tid] = b1[tid];
    if (tid < 50)  sB2c[tid] = b2[tid];
    sGB[tid] = g_gbase[b * G4 + tid];
    sWx[tid] = Wih[tid * (H + 1)];

    const int j8 = tid >> 3, q8 = tid & 7;
    float w1r[25];
    {
        const float* w1p = W1 + j8 * H + q8 * 25;
        #pragma unroll
        for (int k = 0; k < 25; ++k) w1r[k] = w1p[k];
    }
    const float cprev = (tid < H) ? c0in[b * H + tid] : 0.f;
    __syncthreads();

    float xt = x[b];
    const int j16 = tid >> 4, q16 = tid & 15;
    for (int s = 0; s < NSTEP; ++s) {
        if (tid < H) {
            const float gi = sGB[tid]         + xt * sWx[tid];
            const float gf = sGB[H + tid]     + xt * sWx[H + tid];
            const float gg = sGB[2 * H + tid] + xt * sWx[2 * H + tid];
            const float go = sGB[3 * H + tid] + xt * sWx[3 * H + tid];
            const float c  = sig_fast(gf) * cprev + sig_fast(gi) * tanh_fast(gg);
            const float h  = sig_fast(go) * tanh_fast(c);
            sR[tid] = fmaxf(h, 0.f);
        }
        __syncthreads();
        {
            const float* r = sR + q8 * 25;
            float v = 0.f;
            #pragma unroll
            for (int k = 0; k < 25; ++k) v += w1r[k] * r[k];
            v += __shfl_xor_sync(m8, v, 1);
            v += __shfl_xor_sync(m8, v, 2);
            v += __shfl_xor_sync(m8, v, 4);
            if (q8 == 0) sO1[j8] = fmaxf(v + sB1[j8], 0.f);
        }
        __syncthreads();
        {
            const float* w = sW2 + j16 * 100;
            float v = 0.f;
            #pragma unroll
            for (int kk = 0; kk < 7; ++kk) {
                const int k = q16 * 7 + kk;
                if (k < 100) v += w[k] * sO1[k];
            }
            v += __shfl_xor_sync(m16, v, 1);
            v += __shfl_xor_sync(m16, v, 2);
            v += __shfl_xor_sync(m16, v, 4);
            v += __shfl_xor_sync(m16, v, 8);
            if (q16 == 0) sO2[j16] = fmaxf(v + sB2c[j16], 0.f);
        }
        __syncthreads();
        if (tid < 64) sRed[tid] = (tid < 50) ? sW3[tid] * sO2[tid] : 0.f;
        __syncthreads();
        if (tid < 32) {
            float v = sRed[tid] + sRed[tid + 32];
            #pragma unroll
            for (int o = 16; o; o >>= 1) v += __shfl_xor_sync(0xffffffffu, v, o);
            if (tid == 0) { float y = v + b3[0]; out[b * NSTEP + s] = y; sY = y; }
        }
        __syncthreads();
        xt = sY;
    }
}

// ============================================================
extern "C" void kernel_launch(void* const* d_in, const int* in_sizes, int n_in,
                              void* d_out, int out_size) {
    const float* x   = (const float*)d_in[0];
    const float* h0  = (const float*)d_in[1];
    const float* c0  = (const float*)d_in[2];
    const float* enc = (const float*)d_in[3];
    const float* Wa  = (const float*)d_in[4];
    const float* ba  = (const float*)d_in[5];
    const float* Ua  = (const float*)d_in[6];
    const float* bua = (const float*)d_in[7];
    const float* Va  = (const float*)d_in[8];
    // d_in[9] = bva (softmax-shift-invariant, unused)
    const float* Wih = (const float*)d_in[10];
    const float* Whh = (const float*)d_in[11];
    const float* bih = (const float*)d_in[12];
    const float* bhh = (const float*)d_in[13];
    const float* W1  = (const float*)d_in[14];
    const float* b1  = (const float*)d_in[15];
    const float* W2  = (const float*)d_in[16];
    const float* b2  = (const float*)d_in[17];
    const float* W3  = (const float*)d_in[18];
    const float* b3  = (const float*)d_in[19];
    float* out = (float*)d_out;

    cudaFuncSetAttribute(k_scores_mma, cudaFuncAttributeMaxDynamicSharedMemorySize, SMEM_BYTES);

    k_pre<<<dim3(2, 16), dim3(100, 2)>>>(h0, Wa, ba);
    k_scores_mma<<<dim3(T / 128, B), 256, SMEM_BYTES>>>(enc, Ua, bua, Va);
    k_ctx<<<B, CTXTH>>>(enc);
    k_gates<<<dim3(8, 16), dim3(100, 2)>>>(h0, Wih, Whh, bih, bhh);
    k_dec<<<B, G4>>>(x, c0, Wih, W1, b1, W2, b2, W3, b3, out);
}

// round 10
// speedup vs baseline: 1.2047x; 1.2047x over previous
#include <cuda_runtime.h>
#include <cuda_fp16.h>
#include <math.h>
#include <stdint.h>

#define B 128
#define T 2048
#define H 200
#define G4 800
#define NSTEP 5
#define ENC_N (B * T * H)   // 52,428,800

// ---- scratch ----
__device__ float g_qproj[B * H];
__device__ float g_gbase[B * G4];
__device__ float g_spart[2][B * T];
__device__ float g_context[B * H];
__device__ __half g_ench[ENC_N];    // fp16 copy of encoder_output (105 MB)
__device__ __half g_uah[H * H];     // fp16 copy of Ua

__device__ __forceinline__ float tanh_fast(float x) {
    float e = __expf(2.0f * x);
    return 1.0f - __fdividef(2.0f, e + 1.0f);
}
__device__ __forceinline__ float sig_fast(float x) {
    return __fdividef(1.0f, 1.0f + __expf(-x));
}
__device__ __forceinline__ uint32_t smem_u32(const void* p) {
    uint32_t a;
    asm("{ .reg .u64 t; cvta.to.shared.u64 t, %1; cvt.u32.u64 %0, t; }" : "=r"(a) : "l"(p));
    return a;
}
__device__ __forceinline__ void cp_async16(uint32_t dst, const void* src, uint32_t src_sz) {
    asm volatile("cp.async.cg.shared.global [%0], [%1], 16, %2;"
                 :: "r"(dst), "l"(src), "r"(src_sz) : "memory");
}
__device__ __forceinline__ void mma_f16(float* d, const uint32_t* a, const uint32_t* b) {
    asm volatile("mma.sync.aligned.m16n8k16.row.col.f32.f16.f16.f32 "
                 "{%0,%1,%2,%3}, {%4,%5,%6,%7}, {%8,%9}, {%0,%1,%2,%3};"
                 : "+f"(d[0]), "+f"(d[1]), "+f"(d[2]), "+f"(d[3])
                 : "r"(a[0]), "r"(a[1]), "r"(a[2]), "r"(a[3]), "r"(b[0]), "r"(b[1]));
}

// ============================================================
// Kernel 0: fp32 -> fp16 conversion of enc and Ua (one pass, float4 wide)
// ============================================================
#define N4E (ENC_N / 4)        // 13,107,200
#define N4U (H * H / 4)        // 10,000

__global__ void k_cvt(const float* __restrict__ enc, const float* __restrict__ Ua) {
    const long i = (long)blockIdx.x * blockDim.x + threadIdx.x;
    if (i < N4E) {
        float4 v = ((const float4*)enc)[i];
        __half2* d = (__half2*)g_ench;
        d[2 * i]     = __floats2half2_rn(v.x, v.y);
        d[2 * i + 1] = __floats2half2_rn(v.z, v.w);
    } else {
        const long j = i - N4E;
        if (j < N4U) {
            float4 v = ((const float4*)Ua)[j];
            __half2* d = (__half2*)g_uah;
            d[2 * j]     = __floats2half2_rn(v.x, v.y);
            d[2 * j + 1] = __floats2half2_rn(v.z, v.w);
        }
    }
}

// ============================================================
// Kernel 1: qproj = h0 @ Wa.T + ba  (proven simple shape)
// ============================================================
__global__ void k_pre(const float* __restrict__ h0, const float* __restrict__ Wa,
                      const float* __restrict__ ba) {
    __shared__ float q[H];
    const int b = blockIdx.x;
    for (int k = threadIdx.x; k < H; k += blockDim.x) q[k] = h0[b * H + k];
    __syncthreads();
    for (int j = threadIdx.x; j < H; j += blockDim.x) {
        const float* w = Wa + j * H;
        float a0 = 0.f, a1 = 0.f;
        #pragma unroll 4
        for (int k = 0; k < H; k += 2) { a0 += w[k] * q[k]; a1 += w[k + 1] * q[k + 1]; }
        g_qproj[b * H + j] = a0 + a1 + ba[j];
    }
}

// ============================================================
// Kernel 2: score GEMM via mma.sync m16n8k16 FP16 + cp.async double-buffer.
// Grid (T/128, B, 2). Block tile: 128 t x 112 n, K chunks of 32 halves
// (7 chunks, pad 224). fp16 data from g_ench / g_uah.
// Smem rows: 20 words (40 halves; data 32) -> 20q+c mod 32 conflict-free.
// ============================================================
#define NB 112
#define NKCH 7
#define SSTR 20     // row stride in 32-bit words

__global__ __launch_bounds__(256, 2)
void k_scores_mma(const float* __restrict__ bua, const float* __restrict__ Va) {
    __shared__ __align__(16) uint32_t sS[2][(128 + NB) * SSTR];  // 38.4 KB
    __shared__ float sQ[NB];
    __shared__ float sV[NB];
    __shared__ float sRow[128];

    const int tid  = threadIdx.x;
    const int wid  = tid >> 5, lane = tid & 31;
    const int b    = blockIdx.y;
    const int t0   = blockIdx.x * 128;
    const int zi   = blockIdx.z;
    const int n0g  = zi * NB;

    const int mw = wid & 3;
    const int nw = wid >> 2;
    const int rowbase = mw * 32;
    const int nbase   = nw * 56;
    const int q = lane >> 2;
    const int c = lane & 3;

    for (int i = tid; i < NB; i += 256) {
        const int col = n0g + i;
        sQ[i] = (col < H) ? g_qproj[b * H + col] + bua[col] : 0.f;
        sV[i] = (col < H) ? Va[col] : 0.f;
    }
    if (tid < 128) sRow[tid] = 0.f;

    float acc[2][7][4];
    #pragma unroll
    for (int mt = 0; mt < 2; ++mt)
        #pragma unroll
        for (int nt = 0; nt < 7; ++nt)
            #pragma unroll
            for (int j = 0; j < 4; ++j) acc[mt][nt][j] = 0.f;

    const __half* encB = g_ench + ((long)b * T + t0) * H;
    const uint32_t base0 = smem_u32(&sS[0][0]);

    auto fill = [&](int kc, int st) {
        const int k0 = kc * 32;                      // in halves
        const uint32_t stOff = base0 + (uint32_t)st * (128 + NB) * SSTR * 4;
        // A: 128 rows x 4 groups of 8 halves (16B)
        for (int i = tid; i < 128 * 4; i += 256) {
            const int row = i >> 2, g = i & 3;
            const int gk = k0 + g * 8;
            const bool ok = (gk + 8 <= H);
            const void* src = ok ? (const void*)(encB + (long)row * H + gk) : (const void*)encB;
            cp_async16(stOff + (uint32_t)((row * SSTR + g * 4) * 4), src, ok ? 16u : 0u);
        }
        // B: 112 rows x 4 groups
        for (int i = tid; i < NB * 4; i += 256) {
            const int row = i >> 2, g = i & 3;
            const int ng = n0g + row;
            const int gk = k0 + g * 8;
            const bool ok = (ng < H) && (gk + 8 <= H);
            const void* src = ok ? (const void*)(g_uah + (long)ng * H + gk) : (const void*)g_uah;
            cp_async16(stOff + (uint32_t)(((128 + row) * SSTR + g * 4) * 4), src, ok ? 16u : 0u);
        }
        asm volatile("cp.async.commit_group;" ::: "memory");
    };

    fill(0, 0);

    for (int kc = 0; kc < NKCH; ++kc) {
        const int st = kc & 1;
        if (kc + 1 < NKCH) {
            fill(kc + 1, st ^ 1);
            asm volatile("cp.async.wait_group 1;" ::: "memory");
        } else {
            asm volatile("cp.async.wait_group 0;" ::: "memory");
        }
        __syncthreads();

        const uint32_t (*W)[SSTR] = (const uint32_t (*)[SSTR])&sS[st][0];
        #pragma unroll
        for (int ks = 0; ks < 2; ++ks) {
            const int wk = ks * 8;                   // word offset of this k16 step
            uint32_t afr[2][4];
            #pragma unroll
            for (int mt = 0; mt < 2; ++mt) {
                const int R = rowbase + mt * 16 + q;
                afr[mt][0] = W[R][wk + c];
                afr[mt][1] = W[R + 8][wk + c];
                afr[mt][2] = W[R][wk + c + 4];
                afr[mt][3] = W[R + 8][wk + c + 4];
            }
            uint32_t bfr[7][2];
            #pragma unroll
            for (int nt = 0; nt < 7; ++nt) {
                const int N = 128 + nbase + nt * 8 + q;
                bfr[nt][0] = W[N][wk + c];
                bfr[nt][1] = W[N][wk + c + 4];
            }
            #pragma unroll
            for (int mt = 0; mt < 2; ++mt)
                #pragma unroll
                for (int nt = 0; nt < 7; ++nt)
                    mma_f16(acc[mt][nt], afr[mt], bfr[nt]);
        }
        __syncthreads();
    }

    // ---- epilogue: tanh + Va reduce ----
    float pLo[2], pHi[2];
    #pragma unroll
    for (int mt = 0; mt < 2; ++mt) { pLo[mt] = 0.f; pHi[mt] = 0.f; }
    #pragma unroll
    for (int nt = 0; nt < 7; ++nt) {
        const int col0 = nbase + nt * 8 + c * 2;
        const float v0 = sV[col0],     q0 = sQ[col0];
        const float v1 = sV[col0 + 1], q1 = sQ[col0 + 1];
        #pragma unroll
        for (int mt = 0; mt < 2; ++mt) {
            pLo[mt] += v0 * tanh_fast(q0 + acc[mt][nt][0]) + v1 * tanh_fast(q1 + acc[mt][nt][1]);
            pHi[mt] += v0 * tanh_fast(q0 + acc[mt][nt][2]) + v1 * tanh_fast(q1 + acc[mt][nt][3]);
        }
    }
    #pragma unroll
    for (int mt = 0; mt < 2; ++mt) {
        #pragma unroll
        for (int o = 1; o <= 2; o <<= 1) {
            pLo[mt] += __shfl_xor_sync(0xffffffffu, pLo[mt], o);
            pHi[mt] += __shfl_xor_sync(0xffffffffu, pHi[mt], o);
        }
        if (c == 0) {
            const int R = rowbase + mt * 16 + q;
            atomicAdd(&sRow[R], pLo[mt]);
            atomicAdd(&sRow[R + 8], pHi[mt]);
        }
    }
    __syncthreads();
    if (tid < 128) g_spart[zi][b * T + t0 + tid] = sRow[tid];
}

// ============================================================
// Kernel 3: softmax + context. 800 threads = 4 T-slices x 200 h, unroll 8.
// ============================================================
#define CTXTH 800

__global__ void k_ctx(const float* __restrict__ enc) {
    __shared__ float sW[T];
    __shared__ float sP[4][H];
    __shared__ float red[32];
    const int b = blockIdx.x, tid = threadIdx.x;
    const int lane = tid & 31, wid = tid >> 5;

    float m = -1e30f;
    for (int t = tid; t < T; t += CTXTH) {
        float s = g_spart[0][b * T + t] + g_spart[1][b * T + t];
        sW[t] = s; m = fmaxf(m, s);
    }
    #pragma unroll
    for (int o = 16; o; o >>= 1) m = fmaxf(m, __shfl_xor_sync(0xffffffffu, m, o));
    if (lane == 0) red[wid] = m;
    __syncthreads();
    if (tid < 32) {
        float w = (tid < CTXTH / 32) ? red[tid] : -1e30f;
        #pragma unroll
        for (int o = 16; o; o >>= 1) w = fmaxf(w, __shfl_xor_sync(0xffffffffu, w, o));
        if (tid == 0) red[0] = w;
    }
    __syncthreads();
    m = red[0];
    __syncthreads();

    float sum = 0.f;
    for (int t = tid; t < T; t += CTXTH) { float e = __expf(sW[t] - m); sW[t] = e; sum += e; }
    #pragma unroll
    for (int o = 16; o; o >>= 1) sum += __shfl_xor_sync(0xffffffffu, sum, o);
    if (lane == 0) red[wid] = sum;
    __syncthreads();
    if (tid < 32) {
        float w = (tid < CTXTH / 32) ? red[tid] : 0.f;
        #pragma unroll
        for (int o = 16; o; o >>= 1) w += __shfl_xor_sync(0xffffffffu, w, o);
        if (tid == 0) red[0] = w;
    }
    __syncthreads();
    const float inv = __fdividef(1.0f, red[0]);

    const int sl = tid / H;
    const int h  = tid - sl * H;
    const float* eB = enc + (long)b * T * H + h;
    float a[8];
    #pragma unroll
    for (int j = 0; j < 8; ++j) a[j] = 0.f;
    const int tbeg = sl * (T / 4), tend = tbeg + (T / 4);
    for (int t = tbeg; t < tend; t += 8) {
        #pragma unroll
        for (int j = 0; j < 8; ++j) a[j] += sW[t + j] * eB[(long)(t + j) * H];
    }
    sP[sl][h] = ((a[0] + a[1]) + (a[2] + a[3])) + ((a[4] + a[5]) + (a[6] + a[7]));
    __syncthreads();
    if (tid < H)
        g_context[b * H + tid] = (sP[0][tid] + sP[1][tid] + sP[2][tid] + sP[3][tid]) * inv;
}

// ============================================================
// Kernel 3.5: gate base GEMM, v2 — smem-staged coalesced weights.
// grid (8, 16): 100 gate-outputs x 8 batches per block, 800 threads.
// thread = (g_local = tid%100, batch = tid/100); weights chunked k=50.
// ============================================================
__global__ void k_gates(const float* __restrict__ h0, const float* __restrict__ Wih,
                        const float* __restrict__ Whh, const float* __restrict__ bih,
                        const float* __restrict__ bhh) {
    __shared__ float sC[8][200];
    __shared__ float sQT[8][200];
    __shared__ float sW[100][51];    // stride 51 -> conflict-free
    const int tid  = threadIdx.x;
    const int gl   = tid % 100;
    const int bb   = tid / 100;
    const int gBase = blockIdx.x * 100;
    const int b0   = blockIdx.y * 8;
    const int g    = gBase + gl;

    for (int i = tid; i < 8 * 200; i += 800) {
        const int r = i / 200, k = i % 200;
        sC[r][k]  = g_context[(b0 + r) * H + k];
        sQT[r][k] = h0[(b0 + r) * H + k];
    }

    float acc = bih[g] + bhh[g];
    const float* myC = sC[bb];
    const float* myQ = sQT[bb];

    #pragma unroll
    for (int mat = 0; mat < 2; ++mat) {
        #pragma unroll
        for (int ch = 0; ch < 4; ++ch) {
            __syncthreads();
            for (int i = tid; i < 100 * 50; i += 800) {
                const int r = i / 50, cc = i % 50;
                const int gg = gBase + r;
                sW[r][cc] = (mat == 0) ? Wih[gg * (H + 1) + 1 + ch * 50 + cc]
                                       : Whh[gg * H + ch * 50 + cc];
            }
            __syncthreads();
            const float* src = ((mat == 0) ? myC : myQ) + ch * 50;
            float a0 = 0.f, a1 = 0.f;
            #pragma unroll 5
            for (int k = 0; k < 50; k += 2) { a0 += sW[gl][k] * src[k]; a1 += sW[gl][k + 1] * src[k + 1]; }
            acc += a0 + a1;
        }
    }
    g_gbase[(b0 + bb) * G4 + g] = acc;
}

// ============================================================
// Kernel 4: decoder. Gates precomputed; steps touch only smem/regs.
// ============================================================
__global__ void k_dec(const float* __restrict__ x, const float* __restrict__ c0in,
                      const float* __restrict__ Wih,
                      const float* __restrict__ W1, const float* __restrict__ b1,
                      const float* __restrict__ W2, const float* __restrict__ b2,
                      const float* __restrict__ W3, const float* __restrict__ b3,
                      float* __restrict__ out) {
    __shared__ float sGB[G4];
    __shared__ float sWx[G4];
    __shared__ float sR[H];
    __shared__ float sO1[100];
    __shared__ float sO2[52];
    __shared__ float sRed[64];
    __shared__ float sY;
    __shared__ float sW2[5000];
    __shared__ float sW3[52];
    __shared__ float sB1[100];
    __shared__ float sB2c[52];

    const int b = blockIdx.x, tid = threadIdx.x;
    const int lane = tid & 31;
    const unsigned m8  = 0xFFu   << (lane & 24);
    const unsigned m16 = 0xFFFFu << (lane & 16);

    for (int i = tid; i < 5000; i += G4) sW2[i] = W2[i];
    if (tid < 50)  sW3[tid] = W3[tid];
    if (tid < 100) sB1[tid] = b1[tid];
    if (tid < 50)  sB2c[tid] = b2[tid];
    sGB[tid] = g_gbase[b * G4 + tid];
    sWx[tid] = Wih[tid * (H + 1)];

    const int j8 = tid >> 3, q8 = tid & 7;
    float w1r[25];
    {
        const float* w1p = W1 + j8 * H + q8 * 25;
        #pragma unroll
        for (int k = 0; k < 25; ++k) w1r[k] = w1p[k];
    }
    const float cprev = (tid < H) ? c0in[b * H + tid] : 0.f;
    __syncthreads();

    float xt = x[b];
    const int j16 = tid >> 4, q16 = tid & 15;
    for (int s = 0; s < NSTEP; ++s) {
        if (tid < H) {
            const float gi = sGB[tid]         + xt * sWx[tid];
            const float gf = sGB[H + tid]     + xt * sWx[H + tid];
            const float gg = sGB[2 * H + tid] + xt * sWx[2 * H + tid];
            const float go = sGB[3 * H + tid] + xt * sWx[3 * H + tid];
            const float c  = sig_fast(gf) * cprev + sig_fast(gi) * tanh_fast(gg);
            const float h  = sig_fast(go) * tanh_fast(c);
            sR[tid] = fmaxf(h, 0.f);
        }
        __syncthreads();
        {
            const float* r = sR + q8 * 25;
            float v = 0.f;
            #pragma unroll
            for (int k = 0; k < 25; ++k) v += w1r[k] * r[k];
            v += __shfl_xor_sync(m8, v, 1);
            v += __shfl_xor_sync(m8, v, 2);
            v += __shfl_xor_sync(m8, v, 4);
            if (q8 == 0) sO1[j8] = fmaxf(v + sB1[j8], 0.f);
        }
        __syncthreads();
        {
            const float* w = sW2 + j16 * 100;
            float v = 0.f;
            #pragma unroll
            for (int kk = 0; kk < 7; ++kk) {
                const int k = q16 * 7 + kk;
                if (k < 100) v += w[k] * sO1[k];
            }
            v += __shfl_xor_sync(m16, v, 1);
            v += __shfl_xor_sync(m16, v, 2);
            v += __shfl_xor_sync(m16, v, 4);
            v += __shfl_xor_sync(m16, v, 8);
            if (q16 == 0) sO2[j16] = fmaxf(v + sB2c[j16], 0.f);
        }
        __syncthreads();
        if (tid < 64) sRed[tid] = (tid < 50) ? sW3[tid] * sO2[tid] : 0.f;
        __syncthreads();
        if (tid < 32) {
            float v = sRed[tid] + sRed[tid + 32];
            #pragma unroll
            for (int o = 16; o; o >>= 1) v += __shfl_xor_sync(0xffffffffu, v, o);
            if (tid == 0) { float y = v + b3[0]; out[b * NSTEP + s] = y; sY = y; }
        }
        __syncthreads();
        xt = sY;
    }
}

// ============================================================
extern "C" void kernel_launch(void* const* d_in, const int* in_sizes, int n_in,
                              void* d_out, int out_size) {
    const float* x   = (const float*)d_in[0];
    const float* h0  = (const float*)d_in[1];
    const float* c0  = (const float*)d_in[2];
    const float* enc = (const float*)d_in[3];
    const float* Wa  = (const float*)d_in[4];
    const float* ba  = (const float*)d_in[5];
    const float* Ua  = (const float*)d_in[6];
    const float* bua = (const float*)d_in[7];
    const float* Va  = (const float*)d_in[8];
    // d_in[9] = bva (softmax-shift-invariant, unused)
    const float* Wih = (const float*)d_in[10];
    const float* Whh = (const float*)d_in[11];
    const float* bih = (const float*)d_in[12];
    const float* bhh = (const float*)d_in[13];
    const float* W1  = (const float*)d_in[14];
    const float* b1  = (const float*)d_in[15];
    const float* W2  = (const float*)d_in[16];
    const float* b2  = (const float*)d_in[17];
    const float* W3  = (const float*)d_in[18];
    const float* b3  = (const float*)d_in[19];
    float* out = (float*)d_out;

    const long ncvt = N4E + N4U;
    k_cvt<<<(int)((ncvt + 255) / 256), 256>>>(enc, Ua);
    k_pre<<<B, 256>>>(h0, Wa, ba);
    k_scores_mma<<<dim3(T / 128, B, 2), 256>>>(bua, Va);
    k_ctx<<<B, CTXTH>>>(enc);
    k_gates<<<dim3(8, 16), 800>>>(h0, Wih, Whh, bih, bhh);
    k_dec<<<B, G4>>>(x, c0, Wih, W1, b1, W2, b2, W3, b3, out);
}

// round 12
// speedup vs baseline: 1.3426x; 1.1144x over previous
#include <cuda_runtime.h>
#include <cuda_fp16.h>
#include <math.h>
#include <stdint.h>

#define B 128
#define T 2048
#define H 200
#define G4 800
#define NSTEP 5
#define ENC_N (B * T * H)   // 52,428,800

// ---- scratch ----
__device__ float g_qproj[B * H];
__device__ float g_gbase[B * G4];
__device__ float g_spart[2][B * T];
__device__ float g_context[B * H];
__device__ __half g_ench[ENC_N];    // fp16 copy of encoder_output (105 MB)
__device__ __half g_uah[H * H];     // fp16 copy of Ua

__device__ __forceinline__ float tanh_fast(float x) {
    float e = __expf(2.0f * x);
    return 1.0f - __fdividef(2.0f, e + 1.0f);
}
__device__ __forceinline__ float sig_fast(float x) {
    return __fdividef(1.0f, 1.0f + __expf(-x));
}
__device__ __forceinline__ uint32_t smem_u32(const void* p) {
    uint32_t a;
    asm("{ .reg .u64 t; cvta.to.shared.u64 t, %1; cvt.u32.u64 %0, t; }" : "=r"(a) : "l"(p));
    return a;
}
__device__ __forceinline__ void cp_async16(uint32_t dst, const void* src, uint32_t src_sz) {
    asm volatile("cp.async.cg.shared.global [%0], [%1], 16, %2;"
                 :: "r"(dst), "l"(src), "r"(src_sz) : "memory");
}
__device__ __forceinline__ void mma_f16(float* d, const uint32_t* a, const uint32_t* b) {
    asm volatile("mma.sync.aligned.m16n8k16.row.col.f32.f16.f16.f32 "
                 "{%0,%1,%2,%3}, {%4,%5,%6,%7}, {%8,%9}, {%0,%1,%2,%3};"
                 : "+f"(d[0]), "+f"(d[1]), "+f"(d[2]), "+f"(d[3])
                 : "r"(a[0]), "r"(a[1]), "r"(a[2]), "r"(a[3]), "r"(b[0]), "r"(b[1]));
}

// ============================================================
// Kernel 0: fp32 -> fp16 conversion, 8 floats/thread (LDG.128 x2 -> STG.128)
// ============================================================
#define N8E (ENC_N / 8)        // 6,553,600
#define N8U (H * H / 8)        // 5,000

__global__ void k_cvt(const float* __restrict__ enc, const float* __restrict__ Ua) {
    const long i = (long)blockIdx.x * blockDim.x + threadIdx.x;
    const float4* s4;
    uint4* d4;
    long j;
    if (i < N8E)            { s4 = (const float4*)enc; d4 = (uint4*)g_ench; j = i; }
    else if (i - N8E < N8U) { s4 = (const float4*)Ua;  d4 = (uint4*)g_uah;  j = i - N8E; }
    else return;
    float4 v0 = s4[2 * j], v1 = s4[2 * j + 1];
    uint4 o;
    *reinterpret_cast<__half2*>(&o.x) = __floats2half2_rn(v0.x, v0.y);
    *reinterpret_cast<__half2*>(&o.y) = __floats2half2_rn(v0.z, v0.w);
    *reinterpret_cast<__half2*>(&o.z) = __floats2half2_rn(v1.x, v1.y);
    *reinterpret_cast<__half2*>(&o.w) = __floats2half2_rn(v1.z, v1.w);
    d4[j] = o;
}

// ============================================================
// Kernel 1: qproj = h0 @ Wa.T + ba
// ============================================================
__global__ void k_pre(const float* __restrict__ h0, const float* __restrict__ Wa,
                      const float* __restrict__ ba) {
    __shared__ float q[H];
    const int b = blockIdx.x;
    for (int k = threadIdx.x; k < H; k += blockDim.x) q[k] = h0[b * H + k];
    __syncthreads();
    for (int j = threadIdx.x; j < H; j += blockDim.x) {
        const float* w = Wa + j * H;
        float a0 = 0.f, a1 = 0.f;
        #pragma unroll 4
        for (int k = 0; k < H; k += 2) { a0 += w[k] * q[k]; a1 += w[k + 1] * q[k + 1]; }
        g_qproj[b * H + j] = a0 + a1 + ba[j];
    }
}

// ============================================================
// Kernel 2: score GEMM via mma.sync m16n8k16 FP16 + cp.async double-buffer.
// (unchanged — near legacy-HMMA-pipe floor)
// ============================================================
#define NB 112
#define NKCH 7
#define SSTR 20     // row stride in 32-bit words

__global__ __launch_bounds__(256, 2)
void k_scores_mma(const float* __restrict__ bua, const float* __restrict__ Va) {
    __shared__ __align__(16) uint32_t sS[2][(128 + NB) * SSTR];
    __shared__ float sQ[NB];
    __shared__ float sV[NB];
    __shared__ float sRow[128];

    const int tid  = threadIdx.x;
    const int wid  = tid >> 5, lane = tid & 31;
    const int b    = blockIdx.y;
    const int t0   = blockIdx.x * 128;
    const int zi   = blockIdx.z;
    const int n0g  = zi * NB;

    const int mw = wid & 3;
    const int nw = wid >> 2;
    const int rowbase = mw * 32;
    const int nbase   = nw * 56;
    const int q = lane >> 2;
    const int c = lane & 3;

    for (int i = tid; i < NB; i += 256) {
        const int col = n0g + i;
        sQ[i] = (col < H) ? g_qproj[b * H + col] + bua[col] : 0.f;
        sV[i] = (col < H) ? Va[col] : 0.f;
    }
    if (tid < 128) sRow[tid] = 0.f;

    float acc[2][7][4];
    #pragma unroll
    for (int mt = 0; mt < 2; ++mt)
        #pragma unroll
        for (int nt = 0; nt < 7; ++nt)
            #pragma unroll
            for (int j = 0; j < 4; ++j) acc[mt][nt][j] = 0.f;

    const __half* encB = g_ench + ((long)b * T + t0) * H;
    const uint32_t base0 = smem_u32(&sS[0][0]);

    auto fill = [&](int kc, int st) {
        const int k0 = kc * 32;
        const uint32_t stOff = base0 + (uint32_t)st * (128 + NB) * SSTR * 4;
        for (int i = tid; i < 128 * 4; i += 256) {
            const int row = i >> 2, g = i & 3;
            const int gk = k0 + g * 8;
            const bool ok = (gk + 8 <= H);
            const void* src = ok ? (const void*)(encB + (long)row * H + gk) : (const void*)encB;
            cp_async16(stOff + (uint32_t)((row * SSTR + g * 4) * 4), src, ok ? 16u : 0u);
        }
        for (int i = tid; i < NB * 4; i += 256) {
            const int row = i >> 2, g = i & 3;
            const int ng = n0g + row;
            const int gk = k0 + g * 8;
            const bool ok = (ng < H) && (gk + 8 <= H);
            const void* src = ok ? (const void*)(g_uah + (long)ng * H + gk) : (const void*)g_uah;
            cp_async16(stOff + (uint32_t)(((128 + row) * SSTR + g * 4) * 4), src, ok ? 16u : 0u);
        }
        asm volatile("cp.async.commit_group;" ::: "memory");
    };

    fill(0, 0);

    for (int kc = 0; kc < NKCH; ++kc) {
        const int st = kc & 1;
        if (kc + 1 < NKCH) {
            fill(kc + 1, st ^ 1);
            asm volatile("cp.async.wait_group 1;" ::: "memory");
        } else {
            asm volatile("cp.async.wait_group 0;" ::: "memory");
        }
        __syncthreads();

        const uint32_t (*W)[SSTR] = (const uint32_t (*)[SSTR])&sS[st][0];
        #pragma unroll
        for (int ks = 0; ks < 2; ++ks) {
            const int wk = ks * 8;
            uint32_t afr[2][4];
            #pragma unroll
            for (int mt = 0; mt < 2; ++mt) {
                const int R = rowbase + mt * 16 + q;
                afr[mt][0] = W[R][wk + c];
                afr[mt][1] = W[R + 8][wk + c];
                afr[mt][2] = W[R][wk + c + 4];
                afr[mt][3] = W[R + 8][wk + c + 4];
            }
            uint32_t bfr[7][2];
            #pragma unroll
            for (int nt = 0; nt < 7; ++nt) {
                const int N = 128 + nbase + nt * 8 + q;
                bfr[nt][0] = W[N][wk + c];
                bfr[nt][1] = W[N][wk + c + 4];
            }
            #pragma unroll
            for (int mt = 0; mt < 2; ++mt)
                #pragma unroll
                for (int nt = 0; nt < 7; ++nt)
                    mma_f16(acc[mt][nt], afr[mt], bfr[nt]);
        }
        __syncthreads();
    }

    float pLo[2], pHi[2];
    #pragma unroll
    for (int mt = 0; mt < 2; ++mt) { pLo[mt] = 0.f; pHi[mt] = 0.f; }
    #pragma unroll
    for (int nt = 0; nt < 7; ++nt) {
        const int col0 = nbase + nt * 8 + c * 2;
        const float v0 = sV[col0],     q0 = sQ[col0];
        const float v1 = sV[col0 + 1], q1 = sQ[col0 + 1];
        #pragma unroll
        for (int mt = 0; mt < 2; ++mt) {
            pLo[mt] += v0 * tanh_fast(q0 + acc[mt][nt][0]) + v1 * tanh_fast(q1 + acc[mt][nt][1]);
            pHi[mt] += v0 * tanh_fast(q0 + acc[mt][nt][2]) + v1 * tanh_fast(q1 + acc[mt][nt][3]);
        }
    }
    #pragma unroll
    for (int mt = 0; mt < 2; ++mt) {
        #pragma unroll
        for (int o = 1; o <= 2; o <<= 1) {
            pLo[mt] += __shfl_xor_sync(0xffffffffu, pLo[mt], o);
            pHi[mt] += __shfl_xor_sync(0xffffffffu, pHi[mt], o);
        }
        if (c == 0) {
            const int R = rowbase + mt * 16 + q;
            atomicAdd(&sRow[R], pLo[mt]);
            atomicAdd(&sRow[R + 8], pHi[mt]);
        }
    }
    __syncthreads();
    if (tid < 128) g_spart[zi][b * T + t0 + tid] = sRow[tid];
}

// ============================================================
// Kernel 3: softmax + context, fp16 enc (half the DRAM bytes).
// 800 threads = 100 h-pairs x 8 T-slices of 256.
// ============================================================
#define CTXTH 800
#define HP 100          // half-pairs
#define NSL 8           // T-slices
#define TSL (T / NSL)   // 256

__global__ void k_ctx() {
    __shared__ float sW[T];
    __shared__ float sPx[NSL][HP];
    __shared__ float sPy[NSL][HP];
    __shared__ float red[32];
    const int b = blockIdx.x, tid = threadIdx.x;
    const int lane = tid & 31, wid = tid >> 5;

    float m = -1e30f;
    for (int t = tid; t < T; t += CTXTH) {
        float s = g_spart[0][b * T + t] + g_spart[1][b * T + t];
        sW[t] = s; m = fmaxf(m, s);
    }
    #pragma unroll
    for (int o = 16; o; o >>= 1) m = fmaxf(m, __shfl_xor_sync(0xffffffffu, m, o));
    if (lane == 0) red[wid] = m;
    __syncthreads();
    if (tid < 32) {
        float w = (tid < CTXTH / 32) ? red[tid] : -1e30f;
        #pragma unroll
        for (int o = 16; o; o >>= 1) w = fmaxf(w, __shfl_xor_sync(0xffffffffu, w, o));
        if (tid == 0) red[0] = w;
    }
    __syncthreads();
    m = red[0];
    __syncthreads();

    float sum = 0.f;
    for (int t = tid; t < T; t += CTXTH) { float e = __expf(sW[t] - m); sW[t] = e; sum += e; }
    #pragma unroll
    for (int o = 16; o; o >>= 1) sum += __shfl_xor_sync(0xffffffffu, sum, o);
    if (lane == 0) red[wid] = sum;
    __syncthreads();
    if (tid < 32) {
        float w = (tid < CTXTH / 32) ? red[tid] : 0.f;
        #pragma unroll
        for (int o = 16; o; o >>= 1) w += __shfl_xor_sync(0xffffffffu, w, o);
        if (tid == 0) red[0] = w;
    }
    __syncthreads();
    const float inv = __fdividef(1.0f, red[0]);

    // context partials on fp16 enc
    const int sl = tid / HP;          // 0..7
    const int p  = tid - sl * HP;     // 0..99 (pair of h columns)
    const __half2* eB = (const __half2*)g_ench + (long)b * T * HP + p;
    float ax[4], ay[4];
    #pragma unroll
    for (int j = 0; j < 4; ++j) { ax[j] = 0.f; ay[j] = 0.f; }
    const int tbeg = sl * TSL, tend = tbeg + TSL;
    for (int t = tbeg; t < tend; t += 4) {
        #pragma unroll
        for (int j = 0; j < 4; ++j) {
            const float2 v = __half22float2(eB[(long)(t + j) * HP]);
            const float w = sW[t + j];
            ax[j] += w * v.x;
            ay[j] += w * v.y;
        }
    }
    sPx[sl][p] = (ax[0] + ax[1]) + (ax[2] + ax[3]);
    sPy[sl][p] = (ay[0] + ay[1]) + (ay[2] + ay[3]);
    __syncthreads();
    if (tid < H) {
        const int pp = tid >> 1;
        float acc = 0.f;
        if (tid & 1) {
            #pragma unroll
            for (int s = 0; s < NSL; ++s) acc += sPy[s][pp];
        } else {
            #pragma unroll
            for (int s = 0; s < NSL; ++s) acc += sPx[s][pp];
        }
        g_context[b * H + tid] = acc * inv;
    }
}

// ============================================================
// Kernel 3.5: gate base GEMM (smem-staged coalesced weights)
// ============================================================
__global__ void k_gates(const float* __restrict__ h0, const float* __restrict__ Wih,
                        const float* __restrict__ Whh, const float* __restrict__ bih,
                        const float* __restrict__ bhh) {
    __shared__ float sC[8][200];
    __shared__ float sQT[8][200];
    __shared__ float sW[100][51];
    const int tid  = threadIdx.x;
    const int gl   = tid % 100;
    const int bb   = tid / 100;
    const int gBase = blockIdx.x * 100;
    const int b0   = blockIdx.y * 8;
    const int g    = gBase + gl;

    for (int i = tid; i < 8 * 200; i += 800) {
        const int r = i / 200, k = i % 200;
        sC[r][k]  = g_context[(b0 + r) * H + k];
        sQT[r][k] = h0[(b0 + r) * H + k];
    }

    float acc = bih[g] + bhh[g];
    const float* myC = sC[bb];
    const float* myQ = sQT[bb];

    #pragma unroll
    for (int mat = 0; mat < 2; ++mat) {
        #pragma unroll
        for (int ch = 0; ch < 4; ++ch) {
            __syncthreads();
            for (int i = tid; i < 100 * 50; i += 800) {
                const int r = i / 50, cc = i % 50;
                const int gg = gBase + r;
                sW[r][cc] = (mat == 0) ? Wih[gg * (H + 1) + 1 + ch * 50 + cc]
                                       : Whh[gg * H + ch * 50 + cc];
            }
            __syncthreads();
            const float* src = ((mat == 0) ? myC : myQ) + ch * 50;
            float a0 = 0.f, a1 = 0.f;
            #pragma unroll 5
            for (int k = 0; k < 50; k += 2) { a0 += sW[gl][k] * src[k]; a1 += sW[gl][k + 1] * src[k + 1]; }
            acc += a0 + a1;
        }
    }
    g_gbase[(b0 + bb) * G4 + g] = acc;
}

// ============================================================
// Kernel 4: decoder (unchanged)
// ============================================================
__global__ void k_dec(const float* __restrict__ x, const float* __restrict__ c0in,
                      const float* __restrict__ Wih,
                      const float* __restrict__ W1, const float* __restrict__ b1,
                      const float* __restrict__ W2, const float* __restrict__ b2,
                      const float* __restrict__ W3, const float* __restrict__ b3,
                      float* __restrict__ out) {
    __shared__ float sGB[G4];
    __shared__ float sWx[G4];
    __shared__ float sR[H];
    __shared__ float sO1[100];
    __shared__ float sO2[52];
    __shared__ float sRed[64];
    __shared__ float sY;
    __shared__ float sW2[5000];
    __shared__ float sW3[52];
    __shared__ float sB1[100];
    __shared__ float sB2c[52];

    const int b = blockIdx.x, tid = threadIdx.x;
    const int lane = tid & 31;
    const unsigned m8  = 0xFFu   << (lane & 24);
    const unsigned m16 = 0xFFFFu << (lane & 16);

    for (int i = tid; i < 5000; i += G4) sW2[i] = W2[i];
    if (tid < 50)  sW3[tid] = W3[tid];
    if (tid < 100) sB1[tid] = b1[tid];
    if (tid < 50)  sB2c[tid] = b2[tid];
    sGB[tid] = g_gbase[b * G4 + tid];
    sWx[tid] = Wih[tid * (H + 1)];

    const int j8 = tid >> 3, q8 = tid & 7;
    float w1r[25];
    {
        const float* w1p = W1 + j8 * H + q8 * 25;
        #pragma unroll
        for (int k = 0; k < 25; ++k) w1r[k] = w1p[k];
    }
    const float cprev = (tid < H) ? c0in[b * H + tid] : 0.f;
    __syncthreads();

    float xt = x[b];
    const int j16 = tid >> 4, q16 = tid & 15;
    for (int s = 0; s < NSTEP; ++s) {
        if (tid < H) {
            const float gi = sGB[tid]         + xt * sWx[tid];
            const float gf = sGB[H + tid]     + xt * sWx[H + tid];
            const float gg = sGB[2 * H + tid] + xt * sWx[2 * H + tid];
            const float go = sGB[3 * H + tid] + xt * sWx[3 * H + tid];
            const float c  = sig_fast(gf) * cprev + sig_fast(gi) * tanh_fast(gg);
            const float h  = sig_fast(go) * tanh_fast(c);
            sR[tid] = fmaxf(h, 0.f);
        }
        __syncthreads();
        {
            const float* r = sR + q8 * 25;
            float v = 0.f;
            #pragma unroll
            for (int k = 0; k < 25; ++k) v += w1r[k] * r[k];
            v += __shfl_xor_sync(m8, v, 1);
            v += __shfl_xor_sync(m8, v, 2);
            v += __shfl_xor_sync(m8, v, 4);
            if (q8 == 0) sO1[j8] = fmaxf(v + sB1[j8], 0.f);
        }
        __syncthreads();
        {
            const float* w = sW2 + j16 * 100;
            float v = 0.f;
            #pragma unroll
            for (int kk = 0; kk < 7; ++kk) {
                const int k = q16 * 7 + kk;
                if (k < 100) v += w[k] * sO1[k];
            }
            v += __shfl_xor_sync(m16, v, 1);
            v += __shfl_xor_sync(m16, v, 2);
            v += __shfl_xor_sync(m16, v, 4);
            v += __shfl_xor_sync(m16, v, 8);
            if (q16 == 0) sO2[j16] = fmaxf(v + sB2c[j16], 0.f);
        }
        __syncthreads();
        if (tid < 64) sRed[tid] = (tid < 50) ? sW3[tid] * sO2[tid] : 0.f;
        __syncthreads();
        if (tid < 32) {
            float v = sRed[tid] + sRed[tid + 32];
            #pragma unroll
            for (int o = 16; o; o >>= 1) v += __shfl_xor_sync(0xffffffffu, v, o);
            if (tid == 0) { float y = v + b3[0]; out[b * NSTEP + s] = y; sY = y; }
        }
        __syncthreads();
        xt = sY;
    }
}

// ============================================================
extern "C" void kernel_launch(void* const* d_in, const int* in_sizes, int n_in,
                              void* d_out, int out_size) {
    const float* x   = (const float*)d_in[0];
    const float* h0  = (const float*)d_in[1];
    const float* c0  = (const float*)d_in[2];
    const float* enc = (const float*)d_in[3];
    const float* Wa  = (const float*)d_in[4];
    const float* ba  = (const float*)d_in[5];
    const float* Ua  = (const float*)d_in[6];
    const float* bua = (const float*)d_in[7];
    const float* Va  = (const float*)d_in[8];
    // d_in[9] = bva (softmax-shift-invariant, unused)
    const float* Wih = (const float*)d_in[10];
    const float* Whh = (const float*)d_in[11];
    const float* bih = (const float*)d_in[12];
    const float* bhh = (const float*)d_in[13];
    const float* W1  = (const float*)d_in[14];
    const float* b1  = (const float*)d_in[15];
    const float* W2  = (const float*)d_in[16];
    const float* b2  = (const float*)d_in[17];
    const float* W3  = (const float*)d_in[18];
    const float* b3  = (const float*)d_in[19];
    float* out = (float*)d_out;

    const long ncvt = N8E + N8U;
    k_cvt<<<(int)((ncvt + 255) / 256), 256>>>(enc, Ua);
    k_pre<<<B, 256>>>(h0, Wa, ba);
    k_scores_mma<<<dim3(T / 128, B, 2), 256>>>(bua, Va);
    k_ctx<<<B, CTXTH>>>();
    k_gates<<<dim3(8, 16), 800>>>(h0, Wih, Whh, bih, bhh);
    k_dec<<<B, G4>>>(x, c0, Wih, W1, b1, W2, b2, W3, b3, out);
}

// round 13
// speedup vs baseline: 1.4715x; 1.0960x over previous
#include <cuda_runtime.h>
#include <cuda_fp16.h>
#include <math.h>
#include <stdint.h>

#define B 128
#define T 2048
#define H 200
#define G4 800
#define NSTEP 5
#define ENC_N (B * T * H)   // 52,428,800

// ---- scratch ----
__device__ float g_qproj[B * H];
__device__ float g_gbase[B * G4];
__device__ float g_scores[B * T];
__device__ float g_ctxpart[2][B * H];   // per-T-half context partials
__device__ __half g_ench[ENC_N];        // fp16 copy of encoder_output (105 MB)
__device__ __half g_uah[H * H];         // fp16 copy of Ua

__device__ __forceinline__ float tanh_fast(float x) {
    float e = __expf(2.0f * x);
    return 1.0f - __fdividef(2.0f, e + 1.0f);
}
__device__ __forceinline__ float sig_fast(float x) {
    return __fdividef(1.0f, 1.0f + __expf(-x));
}
__device__ __forceinline__ uint32_t smem_u32(const void* p) {
    uint32_t a;
    asm("{ .reg .u64 t; cvta.to.shared.u64 t, %1; cvt.u32.u64 %0, t; }" : "=r"(a) : "l"(p));
    return a;
}
__device__ __forceinline__ void cp_async16(uint32_t dst, const void* src, uint32_t src_sz) {
    asm volatile("cp.async.cg.shared.global [%0], [%1], 16, %2;"
                 :: "r"(dst), "l"(src), "r"(src_sz) : "memory");
}
__device__ __forceinline__ void mma_f16(float* d, const uint32_t* a, const uint32_t* b) {
    asm volatile("mma.sync.aligned.m16n8k16.row.col.f32.f16.f16.f32 "
                 "{%0,%1,%2,%3}, {%4,%5,%6,%7}, {%8,%9}, {%0,%1,%2,%3};"
                 : "+f"(d[0]), "+f"(d[1]), "+f"(d[2]), "+f"(d[3])
                 : "r"(a[0]), "r"(a[1]), "r"(a[2]), "r"(a[3]), "r"(b[0]), "r"(b[1]));
}

// ============================================================
// Kernel 0: fp32 -> fp16 conversion, 8 floats/thread
// ============================================================
#define N8E (ENC_N / 8)
#define N8U (H * H / 8)

__global__ void k_cvt(const float* __restrict__ enc, const float* __restrict__ Ua) {
    const long i = (long)blockIdx.x * blockDim.x + threadIdx.x;
    const float4* s4;
    uint4* d4;
    long j;
    if (i < N8E)            { s4 = (const float4*)enc; d4 = (uint4*)g_ench; j = i; }
    else if (i - N8E < N8U) { s4 = (const float4*)Ua;  d4 = (uint4*)g_uah;  j = i - N8E; }
    else return;
    float4 v0 = s4[2 * j], v1 = s4[2 * j + 1];
    uint4 o;
    *reinterpret_cast<__half2*>(&o.x) = __floats2half2_rn(v0.x, v0.y);
    *reinterpret_cast<__half2*>(&o.y) = __floats2half2_rn(v0.z, v0.w);
    *reinterpret_cast<__half2*>(&o.z) = __floats2half2_rn(v1.x, v1.y);
    *reinterpret_cast<__half2*>(&o.w) = __floats2half2_rn(v1.z, v1.w);
    d4[j] = o;
}

// ============================================================
// Kernel 1: qproj = h0 @ Wa.T + ba
// ============================================================
__global__ void k_pre(const float* __restrict__ h0, const float* __restrict__ Wa,
                      const float* __restrict__ ba) {
    __shared__ float q[H];
    const int b = blockIdx.x;
    for (int k = threadIdx.x; k < H; k += blockDim.x) q[k] = h0[b * H + k];
    __syncthreads();
    for (int j = threadIdx.x; j < H; j += blockDim.x) {
        const float* w = Wa + j * H;
        float a0 = 0.f, a1 = 0.f;
        #pragma unroll 4
        for (int k = 0; k < H; k += 2) { a0 += w[k] * q[k]; a1 += w[k + 1] * q[k + 1]; }
        g_qproj[b * H + j] = a0 + a1 + ba[j];
    }
}

// ============================================================
// Kernel 2: score GEMM, fp16 mma + cp.async double-buffer.
// T-split: block tile 64 t x 224 n (FULL N) -> enc read ONCE (105 MB).
// Grid (T/64, B). 8 warps = 2(m) x 4(n); warp tile 32x56.
// Block writes its 64 score rows directly (no partials).
// ============================================================
#define TMR 64      // t-rows per block
#define NBF 224     // full n (padded)
#define NKCH 7
#define SSTR 20     // row stride in 32-bit words
#define ROWS_ST (TMR + NBF)   // 288 rows per stage

__global__ __launch_bounds__(256)
void k_scores_mma(const float* __restrict__ bua, const float* __restrict__ Va) {
    __shared__ __align__(16) uint32_t sS[2][ROWS_ST * SSTR];  // 46.08 KB
    __shared__ float sQ[NBF];
    __shared__ float sV[NBF];
    __shared__ float sRow[TMR];

    const int tid  = threadIdx.x;
    const int wid  = tid >> 5, lane = tid & 31;
    const int b    = blockIdx.y;
    const int t0   = blockIdx.x * TMR;

    const int mw = wid & 1;            // 2 m-stripes of 32 rows
    const int nw = wid >> 1;           // 4 n-stripes of 56 cols
    const int rowbase = mw * 32;
    const int nbase   = nw * 56;
    const int q = lane >> 2;
    const int c = lane & 3;

    for (int i = tid; i < NBF; i += 256) {
        sQ[i] = (i < H) ? g_qproj[b * H + i] + bua[i] : 0.f;
        sV[i] = (i < H) ? Va[i] : 0.f;
    }
    if (tid < TMR) sRow[tid] = 0.f;

    float acc[2][7][4];
    #pragma unroll
    for (int mt = 0; mt < 2; ++mt)
        #pragma unroll
        for (int nt = 0; nt < 7; ++nt)
            #pragma unroll
            for (int j = 0; j < 4; ++j) acc[mt][nt][j] = 0.f;

    const __half* encB = g_ench + ((long)b * T + t0) * H;
    const uint32_t base0 = smem_u32(&sS[0][0]);

    auto fill = [&](int kc, int st) {
        const int k0 = kc * 32;     // in halves
        const uint32_t stOff = base0 + (uint32_t)st * ROWS_ST * SSTR * 4;
        // A: 64 rows x 4 groups of 8 halves (16B) = 256 -> one per thread
        {
            const int row = tid >> 2, g = tid & 3;
            const int gk = k0 + g * 8;
            const bool ok = (gk + 8 <= H);
            const void* src = ok ? (const void*)(encB + (long)row * H + gk) : (const void*)encB;
            cp_async16(stOff + (uint32_t)((row * SSTR + g * 4) * 4), src, ok ? 16u : 0u);
        }
        // B: 224 rows x 4 groups
        for (int i = tid; i < NBF * 4; i += 256) {
            const int row = i >> 2, g = i & 3;
            const int gk = k0 + g * 8;
            const bool ok = (row < H) && (gk + 8 <= H);
            const void* src = ok ? (const void*)(g_uah + (long)row * H + gk) : (const void*)g_uah;
            cp_async16(stOff + (uint32_t)(((TMR + row) * SSTR + g * 4) * 4), src, ok ? 16u : 0u);
        }
        asm volatile("cp.async.commit_group;" ::: "memory");
    };

    fill(0, 0);

    for (int kc = 0; kc < NKCH; ++kc) {
        const int st = kc & 1;
        if (kc + 1 < NKCH) {
            fill(kc + 1, st ^ 1);
            asm volatile("cp.async.wait_group 1;" ::: "memory");
        } else {
            asm volatile("cp.async.wait_group 0;" ::: "memory");
        }
        __syncthreads();

        const uint32_t (*W)[SSTR] = (const uint32_t (*)[SSTR])&sS[st][0];
        #pragma unroll
        for (int ks = 0; ks < 2; ++ks) {
            const int wk = ks * 8;
            uint32_t afr[2][4];
            #pragma unroll
            for (int mt = 0; mt < 2; ++mt) {
                const int R = rowbase + mt * 16 + q;
                afr[mt][0] = W[R][wk + c];
                afr[mt][1] = W[R + 8][wk + c];
                afr[mt][2] = W[R][wk + c + 4];
                afr[mt][3] = W[R + 8][wk + c + 4];
            }
            uint32_t bfr[7][2];
            #pragma unroll
            for (int nt = 0; nt < 7; ++nt) {
                const int N = TMR + nbase + nt * 8 + q;
                bfr[nt][0] = W[N][wk + c];
                bfr[nt][1] = W[N][wk + c + 4];
            }
            #pragma unroll
            for (int mt = 0; mt < 2; ++mt)
                #pragma unroll
                for (int nt = 0; nt < 7; ++nt)
                    mma_f16(acc[mt][nt], afr[mt], bfr[nt]);
        }
        __syncthreads();
    }

    // ---- epilogue: tanh + Va reduce ----
    float pLo[2], pHi[2];
    #pragma unroll
    for (int mt = 0; mt < 2; ++mt) { pLo[mt] = 0.f; pHi[mt] = 0.f; }
    #pragma unroll
    for (int nt = 0; nt < 7; ++nt) {
        const int col0 = nbase + nt * 8 + c * 2;
        const float v0 = sV[col0],     q0 = sQ[col0];
        const float v1 = sV[col0 + 1], q1 = sQ[col0 + 1];
        #pragma unroll
        for (int mt = 0; mt < 2; ++mt) {
            pLo[mt] += v0 * tanh_fast(q0 + acc[mt][nt][0]) + v1 * tanh_fast(q1 + acc[mt][nt][1]);
            pHi[mt] += v0 * tanh_fast(q0 + acc[mt][nt][2]) + v1 * tanh_fast(q1 + acc[mt][nt][3]);
        }
    }
    #pragma unroll
    for (int mt = 0; mt < 2; ++mt) {
        #pragma unroll
        for (int o = 1; o <= 2; o <<= 1) {
            pLo[mt] += __shfl_xor_sync(0xffffffffu, pLo[mt], o);
            pHi[mt] += __shfl_xor_sync(0xffffffffu, pHi[mt], o);
        }
        if (c == 0) {
            const int R = rowbase + mt * 16 + q;
            atomicAdd(&sRow[R], pLo[mt]);
            atomicAdd(&sRow[R + 8], pHi[mt]);
        }
    }
    __syncthreads();
    if (tid < TMR) g_scores[b * T + t0 + tid] = sRow[tid];
}

// ============================================================
// Kernel 3: softmax + context, fp16 enc, T-split (grid (B, 2)).
// Each block: full-T softmax (scores are L2-hot), context over its T-half.
// 800 threads = 100 h-pairs x 8 slices of 128 t-rows.
// ============================================================
#define CTXTH 800
#define HP 100
#define NSL 8
#define THALF (T / 2)          // 1024
#define TSL (THALF / NSL)      // 128

__global__ void k_ctx() {
    __shared__ float sW[T];
    __shared__ float sPx[NSL][HP];
    __shared__ float sPy[NSL][HP];
    __shared__ float red[32];
    const int b = blockIdx.x, half = blockIdx.y, tid = threadIdx.x;
    const int lane = tid & 31, wid = tid >> 5;

    float m = -1e30f;
    for (int t = tid; t < T; t += CTXTH) { float s = g_scores[b * T + t]; sW[t] = s; m = fmaxf(m, s); }
    #pragma unroll
    for (int o = 16; o; o >>= 1) m = fmaxf(m, __shfl_xor_sync(0xffffffffu, m, o));
    if (lane == 0) red[wid] = m;
    __syncthreads();
    if (tid < 32) {
        float w = (tid < CTXTH / 32) ? red[tid] : -1e30f;
        #pragma unroll
        for (int o = 16; o; o >>= 1) w = fmaxf(w, __shfl_xor_sync(0xffffffffu, w, o));
        if (tid == 0) red[0] = w;
    }
    __syncthreads();
    m = red[0];
    __syncthreads();

    float sum = 0.f;
    for (int t = tid; t < T; t += CTXTH) { float e = __expf(sW[t] - m); sW[t] = e; sum += e; }
    #pragma unroll
    for (int o = 16; o; o >>= 1) sum += __shfl_xor_sync(0xffffffffu, sum, o);
    if (lane == 0) red[wid] = sum;
    __syncthreads();
    if (tid < 32) {
        float w = (tid < CTXTH / 32) ? red[tid] : 0.f;
        #pragma unroll
        for (int o = 16; o; o >>= 1) w += __shfl_xor_sync(0xffffffffu, w, o);
        if (tid == 0) red[0] = w;
    }
    __syncthreads();
    const float inv = __fdividef(1.0f, red[0]);

    // context partial over this block's T-half
    const int sl = tid / HP;          // 0..7
    const int p  = tid - sl * HP;     // 0..99
    const __half2* eB = (const __half2*)g_ench + (long)b * T * HP + p;
    float ax[4], ay[4];
    #pragma unroll
    for (int j = 0; j < 4; ++j) { ax[j] = 0.f; ay[j] = 0.f; }
    const int tbeg = half * THALF + sl * TSL, tend = tbeg + TSL;
    for (int t = tbeg; t < tend; t += 4) {
        #pragma unroll
        for (int j = 0; j < 4; ++j) {
            const float2 v = __half22float2(eB[(long)(t + j) * HP]);
            const float w = sW[t + j];
            ax[j] += w * v.x;
            ay[j] += w * v.y;
        }
    }
    sPx[sl][p] = (ax[0] + ax[1]) + (ax[2] + ax[3]);
    sPy[sl][p] = (ay[0] + ay[1]) + (ay[2] + ay[3]);
    __syncthreads();
    if (tid < H) {
        const int pp = tid >> 1;
        float acc = 0.f;
        if (tid & 1) {
            #pragma unroll
            for (int s = 0; s < NSL; ++s) acc += sPy[s][pp];
        } else {
            #pragma unroll
            for (int s = 0; s < NSL; ++s) acc += sPx[s][pp];
        }
        g_ctxpart[half][b * H + tid] = acc * inv;
    }
}

// ============================================================
// Kernel 3.5: gate base GEMM (sums the two context partials)
// ============================================================
__global__ void k_gates(const float* __restrict__ h0, const float* __restrict__ Wih,
                        const float* __restrict__ Whh, const float* __restrict__ bih,
                        const float* __restrict__ bhh) {
    __shared__ float sC[8][200];
    __shared__ float sQT[8][200];
    __shared__ float sW[100][51];
    const int tid  = threadIdx.x;
    const int gl   = tid % 100;
    const int bb   = tid / 100;
    const int gBase = blockIdx.x * 100;
    const int b0   = blockIdx.y * 8;
    const int g    = gBase + gl;

    for (int i = tid; i < 8 * 200; i += 800) {
        const int r = i / 200, k = i % 200;
        const int idx = (b0 + r) * H + k;
        sC[r][k]  = g_ctxpart[0][idx] + g_ctxpart[1][idx];
        sQT[r][k] = h0[idx];
    }

    float acc = bih[g] + bhh[g];
    const float* myC = sC[bb];
    const float* myQ = sQT[bb];

    #pragma unroll
    for (int mat = 0; mat < 2; ++mat) {
        #pragma unroll
        for (int ch = 0; ch < 4; ++ch) {
            __syncthreads();
            for (int i = tid; i < 100 * 50; i += 800) {
                const int r = i / 50, cc = i % 50;
                const int gg = gBase + r;
                sW[r][cc] = (mat == 0) ? Wih[gg * (H + 1) + 1 + ch * 50 + cc]
                                       : Whh[gg * H + ch * 50 + cc];
            }
            __syncthreads();
            const float* src = ((mat == 0) ? myC : myQ) + ch * 50;
            float a0 = 0.f, a1 = 0.f;
            #pragma unroll 5
            for (int k = 0; k < 50; k += 2) { a0 += sW[gl][k] * src[k]; a1 += sW[gl][k + 1] * src[k + 1]; }
            acc += a0 + a1;
        }
    }
    g_gbase[(b0 + bb) * G4 + g] = acc;
}

// ============================================================
// Kernel 4: decoder (unchanged)
// ============================================================
__global__ void k_dec(const float* __restrict__ x, const float* __restrict__ c0in,
                      const float* __restrict__ Wih,
                      const float* __restrict__ W1, const float* __restrict__ b1,
                      const float* __restrict__ W2, const float* __restrict__ b2,
                      const float* __restrict__ W3, const float* __restrict__ b3,
                      float* __restrict__ out) {
    __shared__ float sGB[G4];
    __shared__ float sWx[G4];
    __shared__ float sR[H];
    __shared__ float sO1[100];
    __shared__ float sO2[52];
    __shared__ float sRed[64];
    __shared__ float sY;
    __shared__ float sW2[5000];
    __shared__ float sW3[52];
    __shared__ float sB1[100];
    __shared__ float sB2c[52];

    const int b = blockIdx.x, tid = threadIdx.x;
    const int lane = tid & 31;
    const unsigned m8  = 0xFFu   << (lane & 24);
    const unsigned m16 = 0xFFFFu << (lane & 16);

    for (int i = tid; i < 5000; i += G4) sW2[i] = W2[i];
    if (tid < 50)  sW3[tid] = W3[tid];
    if (tid < 100) sB1[tid] = b1[tid];
    if (tid < 50)  sB2c[tid] = b2[tid];
    sGB[tid] = g_gbase[b * G4 + tid];
    sWx[tid] = Wih[tid * (H + 1)];

    const int j8 = tid >> 3, q8 = tid & 7;
    float w1r[25];
    {
        const float* w1p = W1 + j8 * H + q8 * 25;
        #pragma unroll
        for (int k = 0; k < 25; ++k) w1r[k] = w1p[k];
    }
    const float cprev = (tid < H) ? c0in[b * H + tid] : 0.f;
    __syncthreads();

    float xt = x[b];
    const int j16 = tid >> 4, q16 = tid & 15;
    for (int s = 0; s < NSTEP; ++s) {
        if (tid < H) {
            const float gi = sGB[tid]         + xt * sWx[tid];
            const float gf = sGB[H + tid]     + xt * sWx[H + tid];
            const float gg = sGB[2 * H + tid] + xt * sWx[2 * H + tid];
            const float go = sGB[3 * H + tid] + xt * sWx[3 * H + tid];
            const float c  = sig_fast(gf) * cprev + sig_fast(gi) * tanh_fast(gg);
            const float h  = sig_fast(go) * tanh_fast(c);
            sR[tid] = fmaxf(h, 0.f);
        }
        __syncthreads();
        {
            const float* r = sR + q8 * 25;
            float v = 0.f;
            #pragma unroll
            for (int k = 0; k < 25; ++k) v += w1r[k] * r[k];
            v += __shfl_xor_sync(m8, v, 1);
            v += __shfl_xor_sync(m8, v, 2);
            v += __shfl_xor_sync(m8, v, 4);
            if (q8 == 0) sO1[j8] = fmaxf(v + sB1[j8], 0.f);
        }
        __syncthreads();
        {
            const float* w = sW2 + j16 * 100;
            float v = 0.f;
            #pragma unroll
            for (int kk = 0; kk < 7; ++kk) {
                const int k = q16 * 7 + kk;
                if (k < 100) v += w[k] * sO1[k];
            }
            v += __shfl_xor_sync(m16, v, 1);
            v += __shfl_xor_sync(m16, v, 2);
            v += __shfl_xor_sync(m16, v, 4);
            v += __shfl_xor_sync(m16, v, 8);
            if (q16 == 0) sO2[j16] = fmaxf(v + sB2c[j16], 0.f);
        }
        __syncthreads();
        if (tid < 64) sRed[tid] = (tid < 50) ? sW3[tid] * sO2[tid] : 0.f;
        __syncthreads();
        if (tid < 32) {
            float v = sRed[tid] + sRed[tid + 32];
            #pragma unroll
            for (int o = 16; o; o >>= 1) v += __shfl_xor_sync(0xffffffffu, v, o);
            if (tid == 0) { float y = v + b3[0]; out[b * NSTEP + s] = y; sY = y; }
        }
        __syncthreads();
        xt = sY;
    }
}

// ============================================================
extern "C" void kernel_launch(void* const* d_in, const int* in_sizes, int n_in,
                              void* d_out, int out_size) {
    const float* x   = (const float*)d_in[0];
    const float* h0  = (const float*)d_in[1];
    const float* c0  = (const float*)d_in[2];
    const float* enc = (const float*)d_in[3];
    const float* Wa  = (const float*)d_in[4];
    const float* ba  = (const float*)d_in[5];
    const float* Ua  = (const float*)d_in[6];
    const float* bua = (const float*)d_in[7];
    const float* Va  = (const float*)d_in[8];
    // d_in[9] = bva (softmax-shift-invariant, unused)
    const float* Wih = (const float*)d_in[10];
    const float* Whh = (const float*)d_in[11];
    const float* bih = (const float*)d_in[12];
    const float* bhh = (const float*)d_in[13];
    const float* W1  = (const float*)d_in[14];
    const float* b1  = (const float*)d_in[15];
    const float* W2  = (const float*)d_in[16];
    const float* b2  = (const float*)d_in[17];
    const float* W3  = (const float*)d_in[18];
    const float* b3  = (const float*)d_in[19];
    float* out = (float*)d_out;

    const long ncvt = N8E + N8U;
    k_cvt<<<(int)((ncvt + 255) / 256), 256>>>(enc, Ua);
    k_pre<<<B, 256>>>(h0, Wa, ba);
    k_scores_mma<<<dim3(T / TMR, B), 256>>>(bua, Va);
    k_ctx<<<dim3(B, 2), CTXTH>>>();
    k_gates<<<dim3(8, 16), 800>>>(h0, Wih, Whh, bih, bhh);
    k_dec<<<B, G4>>>(x, c0, Wih, W1, b1, W2, b2, W3, b3, out);
}